// round 11
// baseline (speedup 1.0000x reference)
#include <cuda_runtime.h>
#include <cuda_bf16.h>
#include <cuda_fp16.h>
#include <cstdint>

// GraphConvolution: out = PReLU( A_coo @ (X @ W^T) + bias )
//   x[40000,512] f32, weight[128,512] f32, bias[128], alpha[1],
//   edge_val[640000] f32, edge_row/col[640000] i32 -> out[40000,128] f32

#define D_IN   512
#define D_OUT  128
#define MAX_NODES 40000
#define MAX_EDGES 640000
#define SCAN_BLOCKS ((MAX_NODES + 1023) / 1024)

// Scratch (device globals: allocation-free rule)
__device__ __half g_seq_h[(size_t)MAX_NODES * D_OUT];   // fp16 seq (10.24 MB)
__device__ int   g_counts[MAX_NODES];
__device__ int   g_row_start[MAX_NODES + 1];
__device__ int   g_cursor[MAX_NODES];
__device__ int2  g_sorted[MAX_EDGES];          // (col, val-bits) packed
__device__ int   g_bsum[SCAN_BLOCKS];
__device__ int   g_boff[SCAN_BLOCKS];
__device__ __half g_wh[D_OUT * D_IN];          // fp16 weight

// ===========================================================================
// Helpers (base-ISA PTX only; must compile at .target sm_103)
// ===========================================================================
__device__ __forceinline__ uint32_t smem_to_u32(const void* p) {
    uint32_t a;
    asm("{ .reg .u64 t; cvta.to.shared.u64 t, %1; cvt.u32.u64 %0, t; }"
        : "=r"(a) : "l"(p));
    return a;
}

#define LDSM_X4(r, addr) \
    asm volatile("ldmatrix.sync.aligned.m8n8.x4.shared.b16 {%0,%1,%2,%3}, [%4];" \
        : "=r"((r)[0]), "=r"((r)[1]), "=r"((r)[2]), "=r"((r)[3]) : "r"(addr))

#define MMA_F16(d, a, b0, b1) \
    asm volatile("mma.sync.aligned.m16n8k16.row.col.f32.f16.f16.f32 " \
        "{%0,%1,%2,%3}, {%4,%5,%6,%7}, {%8,%9}, {%0,%1,%2,%3};" \
        : "+f"((d)[0]), "+f"((d)[1]), "+f"((d)[2]), "+f"((d)[3]) \
        : "r"((a)[0]), "r"((a)[1]), "r"((a)[2]), "r"((a)[3]), "r"(b0), "r"(b1))

#define STS128(addr, r0, r1, r2, r3) \
    asm volatile("st.shared.v4.b32 [%0], {%1, %2, %3, %4};" \
        :: "r"(addr), "r"(r0), "r"(r1), "r"(r2), "r"(r3) : "memory")

#define CP_ASYNC16(dst, src) \
    asm volatile("cp.async.cg.shared.global [%0], [%1], 16;" \
        :: "r"(dst), "l"(src) : "memory")
#define CP_COMMIT() asm volatile("cp.async.commit_group;" ::: "memory")
#define CP_WAIT0()  asm volatile("cp.async.wait_group 0;" ::: "memory")

// 128-byte-row swizzle: bits[6:4] ^= bits[9:7]
#define SW128(off) ((off) ^ (((off) >> 3) & 0x70))

// ===========================================================================
// W prep: f32 -> fp16 once
// ===========================================================================
__global__ void prep_w_kernel(const float* __restrict__ W)
{
    int i = blockIdx.x * blockDim.x + threadIdx.x;  // pairs
    if (i < D_OUT * D_IN / 2) {
        float2 w = reinterpret_cast<const float2*>(W)[i];
        reinterpret_cast<__half2*>(g_wh)[i] = __float22half2_rn(w);
    }
}

// smem layout (bytes): A 2 stages x 16KB, B 2 stages x 16KB
#define SM_A 0
#define SM_B 32768
#define SM_TOTAL 65536

// ===========================================================================
// GEMM: seq_h[M,128] = fp16(X[M,512] @ W^T), single fp16 HMMA
// 128x128 block tile; 8 warps (64x32); K-chunks of 64; A+B double-buffered.
// ===========================================================================
__global__ __launch_bounds__(256, 2) void gemm_mma_kernel(
    const float* __restrict__ X, int M)
{
    extern __shared__ char smem[];
    const uint32_t sb = smem_to_u32(smem);
    const int tid  = threadIdx.x;
    const int lane = tid & 31;
    const int wid  = tid >> 5;
    const int block_m = blockIdx.x * 128;

    const int lrow = tid & 127;          // 2 threads per A row
    const int lcol = (tid >> 7) * 32;    // cols 0-31 / 32-63
    const int a_row = block_m + lrow;
    const bool a_ok = (a_row < M);

    const int wm = (wid & 1) * 64;
    const int wn = (wid >> 1) * 32;

    float acc[4][4][4];
#pragma unroll
    for (int i = 0; i < 4; i++)
#pragma unroll
        for (int j = 0; j < 4; j++)
#pragma unroll
            for (int q = 0; q < 4; q++) acc[i][j][q] = 0.f;

    float4 afa[8];   // prefetched A f32 chunk (32 floats)

    auto load_a = [&](int ch) {
        const int k0 = ch * 64;
#pragma unroll
        for (int j = 0; j < 4; j++) {
            if (a_ok) {
                const float* p = X + (size_t)a_row * D_IN + k0 + lcol + j * 8;
                afa[2*j]   = *reinterpret_cast<const float4*>(p);
                afa[2*j+1] = *reinterpret_cast<const float4*>(p + 4);
            } else {
                afa[2*j] = afa[2*j+1] = make_float4(0.f, 0.f, 0.f, 0.f);
            }
        }
    };

    auto store_a = [&](int st) {
        const uint32_t ab = sb + SM_A + st * 16384;
#pragma unroll
        for (int j = 0; j < 4; j++) {
            const int col = lcol + j * 8;
            const uint32_t off = SW128((uint32_t)(lrow * 128 + col * 2));
            __half2 h0 = __float22half2_rn(make_float2(afa[2*j].x, afa[2*j].y));
            __half2 h1 = __float22half2_rn(make_float2(afa[2*j].z, afa[2*j].w));
            __half2 h2 = __float22half2_rn(make_float2(afa[2*j+1].x, afa[2*j+1].y));
            __half2 h3 = __float22half2_rn(make_float2(afa[2*j+1].z, afa[2*j+1].w));
            STS128(ab + off,
                   *reinterpret_cast<uint32_t*>(&h0), *reinterpret_cast<uint32_t*>(&h1),
                   *reinterpret_cast<uint32_t*>(&h2), *reinterpret_cast<uint32_t*>(&h3));
        }
    };

    auto load_b = [&](int ch, int st) {
        const int k0 = ch * 64;
        const uint32_t bb = sb + SM_B + st * 16384;
#pragma unroll
        for (int it = 0; it < 4; it++) {
            int idx = it * 256 + tid;
            int row = idx >> 3;
            int seg = idx & 7;
            uint32_t off = SW128((uint32_t)(row * 128 + seg * 16));
            CP_ASYNC16(bb + off, g_wh + (size_t)row * D_IN + k0 + seg * 8);
        }
        CP_COMMIT();
    };

    load_a(0);
    load_b(0, 0);

    for (int ch = 0; ch < 8; ch++) {
        const int st = ch & 1;

        store_a(st);                       // overlaps previous chunk's tensor work
        if (ch < 7) load_a(ch + 1);        // LDG prefetch into regs

        CP_WAIT0();                        // B(ch) resident
        __syncthreads();                   // A stores + B visible

        if (ch < 7) load_b(ch + 1, st ^ 1);   // cp.async overlaps MMA

        const uint32_t a_base = sb + SM_A + st * 16384;
        const uint32_t b_base = sb + SM_B + st * 16384;

#pragma unroll
        for (int k16 = 0; k16 < 4; k16++) {
            uint32_t bh[8];
#pragma unroll
            for (int h = 0; h < 2; h++) {
                const int row_b = wn + h * 16 + ((lane >> 4) & 1) * 8 + (lane & 7);
                const int kcol  = k16 * 16 + ((lane >> 3) & 1) * 8;
                const uint32_t off = SW128((uint32_t)(row_b * 128 + kcol * 2));
                LDSM_X4(&bh[h * 4], b_base + off);
            }
#pragma unroll
            for (int am = 0; am < 4; am++) {
                const int row_a = wm + am * 16 + ((lane >> 3) & 1) * 8 + (lane & 7);
                const int kcol  = k16 * 16 + ((lane >> 4) & 1) * 8;
                const uint32_t off = SW128((uint32_t)(row_a * 128 + kcol * 2));
                uint32_t ah[4];
                LDSM_X4(ah, a_base + off);
#pragma unroll
                for (int an = 0; an < 4; an++)
                    MMA_F16(acc[am][an], ah, bh[an*2], bh[an*2+1]);
            }
        }
    }

    // ---- epilogue: f32 acc -> fp16 seq ----
    const int g = lane >> 2;
    const int t = lane & 3;
#pragma unroll
    for (int am = 0; am < 4; am++) {
#pragma unroll
        for (int an = 0; an < 4; an++) {
            const int c  = wn + an * 8 + t * 2;
            const int r0 = block_m + wm + am * 16 + g;
            const int r1 = r0 + 8;
            if (r0 < M) {
                __half2 v = __float22half2_rn(make_float2(acc[am][an][0], acc[am][an][1]));
                *reinterpret_cast<__half2*>(g_seq_h + (size_t)r0 * D_OUT + c) = v;
            }
            if (r1 < M) {
                __half2 v = __float22half2_rn(make_float2(acc[am][an][2], acc[am][an][3]));
                *reinterpret_cast<__half2*>(g_seq_h + (size_t)r1 * D_OUT + c) = v;
            }
        }
    }
}

// ===========================================================================
// CSR build
// ===========================================================================
__global__ void zero_counts_kernel(int n)
{
    int i = blockIdx.x * blockDim.x + threadIdx.x;
    if (i < n) g_counts[i] = 0;
}

__global__ void hist_kernel(const int* __restrict__ edge_row, int E)
{
    int i = blockIdx.x * blockDim.x + threadIdx.x;
    if (i < E) atomicAdd(&g_counts[edge_row[i]], 1);
}

__global__ __launch_bounds__(1024) void block_sum_kernel(int n)
{
    int gid = blockIdx.x * 1024 + threadIdx.x;
    int c = (gid < n) ? g_counts[gid] : 0;
    const int lane = threadIdx.x & 31, w = threadIdx.x >> 5;
#pragma unroll
    for (int o = 16; o > 0; o >>= 1) c += __shfl_down_sync(0xFFFFFFFFu, c, o);
    __shared__ int ws[32];
    if (lane == 0) ws[w] = c;
    __syncthreads();
    if (w == 0) {
        int v = ws[lane];
#pragma unroll
        for (int o = 16; o > 0; o >>= 1) v += __shfl_down_sync(0xFFFFFFFFu, v, o);
        if (lane == 0) g_bsum[blockIdx.x] = v;
    }
}

__global__ void bsum_scan_kernel(int nb, int n)
{
    const int tid = threadIdx.x;                 // 64 threads
    int v = (tid < nb) ? g_bsum[tid] : 0;
    const int lane = tid & 31, w = tid >> 5;
    int x = v;
#pragma unroll
    for (int o = 1; o < 32; o <<= 1) {
        int y = __shfl_up_sync(0xFFFFFFFFu, x, o);
        if (lane >= o) x += y;
    }
    __shared__ int ws[2];
    if (lane == 31) ws[w] = x;
    __syncthreads();
    if (w == 1) x += ws[0];
    if (tid < nb) g_boff[tid] = x - v;
    if (tid == nb - 1) g_row_start[n] = x;
}

__global__ __launch_bounds__(1024) void scan_pass3_kernel(int n)
{
    int gid = blockIdx.x * 1024 + threadIdx.x;
    int c = (gid < n) ? g_counts[gid] : 0;
    const int lane = threadIdx.x & 31, w = threadIdx.x >> 5;
    int x = c;
#pragma unroll
    for (int o = 1; o < 32; o <<= 1) {
        int y = __shfl_up_sync(0xFFFFFFFFu, x, o);
        if (lane >= o) x += y;
    }
    __shared__ int ws[32];
    if (lane == 31) ws[w] = x;
    __syncthreads();
    if (w == 0) {
        int y = ws[lane];
#pragma unroll
        for (int o = 1; o < 32; o <<= 1) {
            int z = __shfl_up_sync(0xFFFFFFFFu, y, o);
            if (lane >= o) y += z;
        }
        ws[lane] = y;
    }
    __syncthreads();
    int excl = x - c + (w ? ws[w - 1] : 0) + g_boff[blockIdx.x];
    if (gid < n) { g_row_start[gid] = excl; g_cursor[gid] = excl; }
}

__global__ void bucket_kernel(const float* __restrict__ edge_val,
                              const int*   __restrict__ edge_row,
                              const int*   __restrict__ edge_col, int E)
{
    int i = blockIdx.x * blockDim.x + threadIdx.x;
    if (i >= E) return;
    int r = edge_row[i];
    int pos = atomicAdd(&g_cursor[r], 1);
    g_sorted[pos] = make_int2(edge_col[i], __float_as_int(edge_val[i]));
}

// ===========================================================================
// Gather: one warp per row; fp16 seq reads; f32 accumulate; bias + PReLU
// ===========================================================================
__device__ __forceinline__ void gacc(float4& acc, float v, uint2 raw) {
    __half2 h0 = *reinterpret_cast<__half2*>(&raw.x);
    __half2 h1 = *reinterpret_cast<__half2*>(&raw.y);
    float2 f0 = __half22float2(h0);
    float2 f1 = __half22float2(h1);
    acc.x = fmaf(v, f0.x, acc.x); acc.y = fmaf(v, f0.y, acc.y);
    acc.z = fmaf(v, f1.x, acc.z); acc.w = fmaf(v, f1.y, acc.w);
}

__global__ __launch_bounds__(256) void gather_kernel(
    const float* __restrict__ bias,
    const float* __restrict__ alpha,
    float* __restrict__ out, int n_nodes)
{
    int w = blockIdx.x * (blockDim.x >> 5) + (threadIdx.x >> 5);
    if (w >= n_nodes) return;
    const int lane = threadIdx.x & 31;

    const int s = g_row_start[w];
    const int e = g_row_start[w + 1];

    float4 acc = make_float4(0.f, 0.f, 0.f, 0.f);
    int i = s;
    for (; i + 3 < e; i += 4) {
        int2 p0 = g_sorted[i],   p1 = g_sorted[i+1];
        int2 p2 = g_sorted[i+2], p3 = g_sorted[i+3];
        uint2 r0 = *reinterpret_cast<const uint2*>(g_seq_h + (size_t)p0.x * D_OUT + lane * 4);
        uint2 r1 = *reinterpret_cast<const uint2*>(g_seq_h + (size_t)p1.x * D_OUT + lane * 4);
        uint2 r2 = *reinterpret_cast<const uint2*>(g_seq_h + (size_t)p2.x * D_OUT + lane * 4);
        uint2 r3 = *reinterpret_cast<const uint2*>(g_seq_h + (size_t)p3.x * D_OUT + lane * 4);
        gacc(acc, __int_as_float(p0.y), r0);
        gacc(acc, __int_as_float(p1.y), r1);
        gacc(acc, __int_as_float(p2.y), r2);
        gacc(acc, __int_as_float(p3.y), r3);
    }
    for (; i < e; i++) {
        int2 p = g_sorted[i];
        uint2 r = *reinterpret_cast<const uint2*>(g_seq_h + (size_t)p.x * D_OUT + lane * 4);
        gacc(acc, __int_as_float(p.y), r);
    }

    const float a = alpha[0];
    float4 b = *reinterpret_cast<const float4*>(bias + lane * 4);
    acc.x += b.x; acc.y += b.y; acc.z += b.z; acc.w += b.w;
    acc.x = acc.x > 0.f ? acc.x : a * acc.x;
    acc.y = acc.y > 0.f ? acc.y : a * acc.y;
    acc.z = acc.z > 0.f ? acc.z : a * acc.z;
    acc.w = acc.w > 0.f ? acc.w : a * acc.w;

    *reinterpret_cast<float4*>(out + (size_t)w * D_OUT + lane * 4) = acc;
}

// ===========================================================================
extern "C" void kernel_launch(void* const* d_in, const int* in_sizes, int n_in,
                              void* d_out, int out_size)
{
    const float* x        = (const float*)d_in[0];
    const float* weight   = (const float*)d_in[1];
    const float* bias     = (const float*)d_in[2];
    const float* alpha    = (const float*)d_in[3];
    const float* edge_val = (const float*)d_in[4];
    const int*   edge_row = (const int*)d_in[5];
    const int*   edge_col = (const int*)d_in[6];
    float*       out      = (float*)d_out;

    const int n_nodes = in_sizes[0] / D_IN;     // 40000
    const int n_edges = in_sizes[4];            // 640000

    static cudaStream_t s2 = nullptr;
    static cudaEvent_t evA = nullptr, evB = nullptr;
    static bool init_done = false;
    if (!init_done) {
        cudaStreamCreateWithFlags(&s2, cudaStreamNonBlocking);
        cudaEventCreateWithFlags(&evA, cudaEventDisableTiming);
        cudaEventCreateWithFlags(&evB, cudaEventDisableTiming);
        cudaFuncSetAttribute(gemm_mma_kernel,
                             cudaFuncAttributeMaxDynamicSharedMemorySize, SM_TOTAL);
        init_done = true;
    }

    // fork: CSR build on s2 runs concurrently with GEMM on the main stream
    cudaEventRecord(evA, 0);
    cudaStreamWaitEvent(s2, evA, 0);

    // --- main stream: W prep + GEMM ---
    prep_w_kernel<<<(D_OUT * D_IN / 2 + 255) / 256, 256>>>(weight);
    gemm_mma_kernel<<<(n_nodes + 127) / 128, 256, SM_TOTAL>>>(x, n_nodes);

    // --- s2: CSR build ---
    zero_counts_kernel<<<(n_nodes + 255) / 256, 256, 0, s2>>>(n_nodes);
    hist_kernel<<<(n_edges + 255) / 256, 256, 0, s2>>>(edge_row, n_edges);
    {
        int nb = (n_nodes + 1023) / 1024;
        block_sum_kernel<<<nb, 1024, 0, s2>>>(n_nodes);
        bsum_scan_kernel<<<1, 64, 0, s2>>>(nb, n_nodes);
        scan_pass3_kernel<<<nb, 1024, 0, s2>>>(n_nodes);
    }
    bucket_kernel<<<(n_edges + 255) / 256, 256, 0, s2>>>(edge_val, edge_row, edge_col, n_edges);
    cudaEventRecord(evB, s2);

    // join, then gather
    cudaStreamWaitEvent(0, evB, 0);
    {
        int warps_per_block = 256 / 32;
        int grid = (n_nodes + warps_per_block - 1) / warps_per_block;
        gather_kernel<<<grid, 256>>>(bias, alpha, out, n_nodes);
    }
}

// round 12
// speedup vs baseline: 1.5610x; 1.5610x over previous
#include <cuda_runtime.h>
#include <cuda_bf16.h>
#include <cuda_fp16.h>
#include <cstdint>

// GraphConvolution: out = PReLU( A_coo @ (X @ W^T) + bias )
//   x[40000,512] f32, weight[128,512] f32, bias[128], alpha[1],
//   edge_val[640000] f32, edge_row/col[640000] i32 -> out[40000,128] f32

#define D_IN   512
#define D_OUT  128
#define MAX_NODES 40000
#define MAX_EDGES 640000
#define SCAN_BLOCKS ((MAX_NODES + 1023) / 1024)

// Scratch (device globals: allocation-free rule)
__device__ __half g_seq_h[(size_t)MAX_NODES * D_OUT];   // fp16 seq (10.24 MB)
__device__ int   g_counts[MAX_NODES];
__device__ int   g_row_start[MAX_NODES + 1];
__device__ int   g_cursor[MAX_NODES];
__device__ int2  g_sorted[MAX_EDGES];          // (col, val-bits) packed
__device__ int   g_bsum[SCAN_BLOCKS];
__device__ int   g_boff[SCAN_BLOCKS];
__device__ __half g_wh[D_OUT * D_IN];          // fp16 weight

// ===========================================================================
// Helpers (base-ISA PTX only; must compile at .target sm_103)
// ===========================================================================
__device__ __forceinline__ uint32_t smem_to_u32(const void* p) {
    uint32_t a;
    asm("{ .reg .u64 t; cvta.to.shared.u64 t, %1; cvt.u32.u64 %0, t; }"
        : "=r"(a) : "l"(p));
    return a;
}

#define LDSM_X4(r, addr) \
    asm volatile("ldmatrix.sync.aligned.m8n8.x4.shared.b16 {%0,%1,%2,%3}, [%4];" \
        : "=r"((r)[0]), "=r"((r)[1]), "=r"((r)[2]), "=r"((r)[3]) : "r"(addr))

#define MMA_F16(d, a, b0, b1) \
    asm volatile("mma.sync.aligned.m16n8k16.row.col.f32.f16.f16.f32 " \
        "{%0,%1,%2,%3}, {%4,%5,%6,%7}, {%8,%9}, {%0,%1,%2,%3};" \
        : "+f"((d)[0]), "+f"((d)[1]), "+f"((d)[2]), "+f"((d)[3]) \
        : "r"((a)[0]), "r"((a)[1]), "r"((a)[2]), "r"((a)[3]), "r"(b0), "r"(b1))

#define STS128(addr, r0, r1, r2, r3) \
    asm volatile("st.shared.v4.b32 [%0], {%1, %2, %3, %4};" \
        :: "r"(addr), "r"(r0), "r"(r1), "r"(r2), "r"(r3) : "memory")

#define CP_ASYNC16(dst, src) \
    asm volatile("cp.async.cg.shared.global [%0], [%1], 16;" \
        :: "r"(dst), "l"(src) : "memory")
#define CP_COMMIT() asm volatile("cp.async.commit_group;" ::: "memory")
#define CP_WAIT0()  asm volatile("cp.async.wait_group 0;" ::: "memory")

// 128-byte-row swizzle: bits[6:4] ^= bits[9:7]
#define SW128(off) ((off) ^ (((off) >> 3) & 0x70))

// ===========================================================================
// W prep: f32 -> fp16 once
// ===========================================================================
__global__ void prep_w_kernel(const float* __restrict__ W)
{
    int i = blockIdx.x * blockDim.x + threadIdx.x;  // pairs
    if (i < D_OUT * D_IN / 2) {
        float2 w = reinterpret_cast<const float2*>(W)[i];
        reinterpret_cast<__half2*>(g_wh)[i] = __float22half2_rn(w);
    }
}

// smem layout (bytes): A 2 stages x 16KB, B 2 stages x 16KB
#define SM_A 0
#define SM_B 32768
#define SM_TOTAL 65536

// ===========================================================================
// GEMM: seq_h[M,128] = fp16(X[M,512] @ W^T), single fp16 HMMA
// 128x128 block tile; 8 warps (64x32); K-chunks of 64; A+B double-buffered.
// NOTE: no min-blocks in launch_bounds — forcing 2 blocks/SM caps regs at 128
// and spills the accumulators (R10 regression, 130 us).
// ===========================================================================
__global__ __launch_bounds__(256) void gemm_mma_kernel(
    const float* __restrict__ X, int M)
{
    extern __shared__ char smem[];
    const uint32_t sb = smem_to_u32(smem);
    const int tid  = threadIdx.x;
    const int lane = tid & 31;
    const int wid  = tid >> 5;
    const int block_m = blockIdx.x * 128;

    const int lrow = tid & 127;          // 2 threads per A row
    const int lcol = (tid >> 7) * 32;    // cols 0-31 / 32-63
    const int a_row = block_m + lrow;
    const bool a_ok = (a_row < M);

    const int wm = (wid & 1) * 64;
    const int wn = (wid >> 1) * 32;

    float acc[4][4][4];
#pragma unroll
    for (int i = 0; i < 4; i++)
#pragma unroll
        for (int j = 0; j < 4; j++)
#pragma unroll
            for (int q = 0; q < 4; q++) acc[i][j][q] = 0.f;

    float4 afa[8];   // prefetched A f32 chunk (32 floats)

    auto load_a = [&](int ch) {
        const int k0 = ch * 64;
#pragma unroll
        for (int j = 0; j < 4; j++) {
            if (a_ok) {
                const float* p = X + (size_t)a_row * D_IN + k0 + lcol + j * 8;
                afa[2*j]   = *reinterpret_cast<const float4*>(p);
                afa[2*j+1] = *reinterpret_cast<const float4*>(p + 4);
            } else {
                afa[2*j] = afa[2*j+1] = make_float4(0.f, 0.f, 0.f, 0.f);
            }
        }
    };

    auto store_a = [&](int st) {
        const uint32_t ab = sb + SM_A + st * 16384;
#pragma unroll
        for (int j = 0; j < 4; j++) {
            const int col = lcol + j * 8;
            const uint32_t off = SW128((uint32_t)(lrow * 128 + col * 2));
            __half2 h0 = __float22half2_rn(make_float2(afa[2*j].x, afa[2*j].y));
            __half2 h1 = __float22half2_rn(make_float2(afa[2*j].z, afa[2*j].w));
            __half2 h2 = __float22half2_rn(make_float2(afa[2*j+1].x, afa[2*j+1].y));
            __half2 h3 = __float22half2_rn(make_float2(afa[2*j+1].z, afa[2*j+1].w));
            STS128(ab + off,
                   *reinterpret_cast<uint32_t*>(&h0), *reinterpret_cast<uint32_t*>(&h1),
                   *reinterpret_cast<uint32_t*>(&h2), *reinterpret_cast<uint32_t*>(&h3));
        }
    };

    auto load_b = [&](int ch, int st) {
        const int k0 = ch * 64;
        const uint32_t bb = sb + SM_B + st * 16384;
#pragma unroll
        for (int it = 0; it < 4; it++) {
            int idx = it * 256 + tid;
            int row = idx >> 3;
            int seg = idx & 7;
            uint32_t off = SW128((uint32_t)(row * 128 + seg * 16));
            CP_ASYNC16(bb + off, g_wh + (size_t)row * D_IN + k0 + seg * 8);
        }
        CP_COMMIT();
    };

    load_a(0);
    load_b(0, 0);

    for (int ch = 0; ch < 8; ch++) {
        const int st = ch & 1;

        store_a(st);                       // overlaps previous chunk's tensor work
        if (ch < 7) load_a(ch + 1);        // LDG prefetch into regs

        CP_WAIT0();                        // B(ch) resident
        __syncthreads();                   // A stores + B visible

        if (ch < 7) load_b(ch + 1, st ^ 1);   // cp.async overlaps MMA

        const uint32_t a_base = sb + SM_A + st * 16384;
        const uint32_t b_base = sb + SM_B + st * 16384;

#pragma unroll
        for (int k16 = 0; k16 < 4; k16++) {
            uint32_t bh[8];
#pragma unroll
            for (int h = 0; h < 2; h++) {
                const int row_b = wn + h * 16 + ((lane >> 4) & 1) * 8 + (lane & 7);
                const int kcol  = k16 * 16 + ((lane >> 3) & 1) * 8;
                const uint32_t off = SW128((uint32_t)(row_b * 128 + kcol * 2));
                LDSM_X4(&bh[h * 4], b_base + off);
            }
#pragma unroll
            for (int am = 0; am < 4; am++) {
                const int row_a = wm + am * 16 + ((lane >> 3) & 1) * 8 + (lane & 7);
                const int kcol  = k16 * 16 + ((lane >> 4) & 1) * 8;
                const uint32_t off = SW128((uint32_t)(row_a * 128 + kcol * 2));
                uint32_t ah[4];
                LDSM_X4(ah, a_base + off);
#pragma unroll
                for (int an = 0; an < 4; an++)
                    MMA_F16(acc[am][an], ah, bh[an*2], bh[an*2+1]);
            }
        }
    }

    // ---- epilogue: f32 acc -> fp16 seq ----
    const int g = lane >> 2;
    const int t = lane & 3;
#pragma unroll
    for (int am = 0; am < 4; am++) {
#pragma unroll
        for (int an = 0; an < 4; an++) {
            const int c  = wn + an * 8 + t * 2;
            const int r0 = block_m + wm + am * 16 + g;
            const int r1 = r0 + 8;
            if (r0 < M) {
                __half2 v = __float22half2_rn(make_float2(acc[am][an][0], acc[am][an][1]));
                *reinterpret_cast<__half2*>(g_seq_h + (size_t)r0 * D_OUT + c) = v;
            }
            if (r1 < M) {
                __half2 v = __float22half2_rn(make_float2(acc[am][an][2], acc[am][an][3]));
                *reinterpret_cast<__half2*>(g_seq_h + (size_t)r1 * D_OUT + c) = v;
            }
        }
    }
}

// ===========================================================================
// CSR build
// ===========================================================================
__global__ void zero_counts_kernel(int n)
{
    int i = blockIdx.x * blockDim.x + threadIdx.x;
    if (i < n) g_counts[i] = 0;
}

__global__ void hist_kernel(const int* __restrict__ edge_row, int E)
{
    int i = blockIdx.x * blockDim.x + threadIdx.x;
    if (i < E) atomicAdd(&g_counts[edge_row[i]], 1);
}

__global__ __launch_bounds__(1024) void block_sum_kernel(int n)
{
    int gid = blockIdx.x * 1024 + threadIdx.x;
    int c = (gid < n) ? g_counts[gid] : 0;
    const int lane = threadIdx.x & 31, w = threadIdx.x >> 5;
#pragma unroll
    for (int o = 16; o > 0; o >>= 1) c += __shfl_down_sync(0xFFFFFFFFu, c, o);
    __shared__ int ws[32];
    if (lane == 0) ws[w] = c;
    __syncthreads();
    if (w == 0) {
        int v = ws[lane];
#pragma unroll
        for (int o = 16; o > 0; o >>= 1) v += __shfl_down_sync(0xFFFFFFFFu, v, o);
        if (lane == 0) g_bsum[blockIdx.x] = v;
    }
}

__global__ void bsum_scan_kernel(int nb, int n)
{
    const int tid = threadIdx.x;                 // 64 threads
    int v = (tid < nb) ? g_bsum[tid] : 0;
    const int lane = tid & 31, w = tid >> 5;
    int x = v;
#pragma unroll
    for (int o = 1; o < 32; o <<= 1) {
        int y = __shfl_up_sync(0xFFFFFFFFu, x, o);
        if (lane >= o) x += y;
    }
    __shared__ int ws[2];
    if (lane == 31) ws[w] = x;
    __syncthreads();
    if (w == 1) x += ws[0];
    if (tid < nb) g_boff[tid] = x - v;
    if (tid == nb - 1) g_row_start[n] = x;
}

__global__ __launch_bounds__(1024) void scan_pass3_kernel(int n)
{
    int gid = blockIdx.x * 1024 + threadIdx.x;
    int c = (gid < n) ? g_counts[gid] : 0;
    const int lane = threadIdx.x & 31, w = threadIdx.x >> 5;
    int x = c;
#pragma unroll
    for (int o = 1; o < 32; o <<= 1) {
        int y = __shfl_up_sync(0xFFFFFFFFu, x, o);
        if (lane >= o) x += y;
    }
    __shared__ int ws[32];
    if (lane == 31) ws[w] = x;
    __syncthreads();
    if (w == 0) {
        int y = ws[lane];
#pragma unroll
        for (int o = 1; o < 32; o <<= 1) {
            int z = __shfl_up_sync(0xFFFFFFFFu, y, o);
            if (lane >= o) y += z;
        }
        ws[lane] = y;
    }
    __syncthreads();
    int excl = x - c + (w ? ws[w - 1] : 0) + g_boff[blockIdx.x];
    if (gid < n) { g_row_start[gid] = excl; g_cursor[gid] = excl; }
}

__global__ void bucket_kernel(const float* __restrict__ edge_val,
                              const int*   __restrict__ edge_row,
                              const int*   __restrict__ edge_col, int E)
{
    int i = blockIdx.x * blockDim.x + threadIdx.x;
    if (i >= E) return;
    int r = edge_row[i];
    int pos = atomicAdd(&g_cursor[r], 1);
    g_sorted[pos] = make_int2(edge_col[i], __float_as_int(edge_val[i]));
}

// ===========================================================================
// Gather: one warp per row; fp16 seq reads; f32 accumulate; bias + PReLU
// ===========================================================================
__device__ __forceinline__ void gacc(float4& acc, float v, uint2 raw) {
    __half2 h0 = *reinterpret_cast<__half2*>(&raw.x);
    __half2 h1 = *reinterpret_cast<__half2*>(&raw.y);
    float2 f0 = __half22float2(h0);
    float2 f1 = __half22float2(h1);
    acc.x = fmaf(v, f0.x, acc.x); acc.y = fmaf(v, f0.y, acc.y);
    acc.z = fmaf(v, f1.x, acc.z); acc.w = fmaf(v, f1.y, acc.w);
}

__global__ __launch_bounds__(256) void gather_kernel(
    const float* __restrict__ bias,
    const float* __restrict__ alpha,
    float* __restrict__ out, int n_nodes)
{
    int w = blockIdx.x * (blockDim.x >> 5) + (threadIdx.x >> 5);
    if (w >= n_nodes) return;
    const int lane = threadIdx.x & 31;

    const int s = g_row_start[w];
    const int e = g_row_start[w + 1];

    float4 acc = make_float4(0.f, 0.f, 0.f, 0.f);
    int i = s;
    for (; i + 3 < e; i += 4) {
        int2 p0 = g_sorted[i],   p1 = g_sorted[i+1];
        int2 p2 = g_sorted[i+2], p3 = g_sorted[i+3];
        uint2 r0 = *reinterpret_cast<const uint2*>(g_seq_h + (size_t)p0.x * D_OUT + lane * 4);
        uint2 r1 = *reinterpret_cast<const uint2*>(g_seq_h + (size_t)p1.x * D_OUT + lane * 4);
        uint2 r2 = *reinterpret_cast<const uint2*>(g_seq_h + (size_t)p2.x * D_OUT + lane * 4);
        uint2 r3 = *reinterpret_cast<const uint2*>(g_seq_h + (size_t)p3.x * D_OUT + lane * 4);
        gacc(acc, __int_as_float(p0.y), r0);
        gacc(acc, __int_as_float(p1.y), r1);
        gacc(acc, __int_as_float(p2.y), r2);
        gacc(acc, __int_as_float(p3.y), r3);
    }
    for (; i < e; i++) {
        int2 p = g_sorted[i];
        uint2 r = *reinterpret_cast<const uint2*>(g_seq_h + (size_t)p.x * D_OUT + lane * 4);
        gacc(acc, __int_as_float(p.y), r);
    }

    const float a = alpha[0];
    float4 b = *reinterpret_cast<const float4*>(bias + lane * 4);
    acc.x += b.x; acc.y += b.y; acc.z += b.z; acc.w += b.w;
    acc.x = acc.x > 0.f ? acc.x : a * acc.x;
    acc.y = acc.y > 0.f ? acc.y : a * acc.y;
    acc.z = acc.z > 0.f ? acc.z : a * acc.z;
    acc.w = acc.w > 0.f ? acc.w : a * acc.w;

    *reinterpret_cast<float4*>(out + (size_t)w * D_OUT + lane * 4) = acc;
}

// ===========================================================================
extern "C" void kernel_launch(void* const* d_in, const int* in_sizes, int n_in,
                              void* d_out, int out_size)
{
    const float* x        = (const float*)d_in[0];
    const float* weight   = (const float*)d_in[1];
    const float* bias     = (const float*)d_in[2];
    const float* alpha    = (const float*)d_in[3];
    const float* edge_val = (const float*)d_in[4];
    const int*   edge_row = (const int*)d_in[5];
    const int*   edge_col = (const int*)d_in[6];
    float*       out      = (float*)d_out;

    const int n_nodes = in_sizes[0] / D_IN;     // 40000
    const int n_edges = in_sizes[4];            // 640000

    static cudaStream_t s2 = nullptr;
    static cudaEvent_t evA = nullptr, evB = nullptr;
    static bool init_done = false;
    if (!init_done) {
        cudaStreamCreateWithFlags(&s2, cudaStreamNonBlocking);
        cudaEventCreateWithFlags(&evA, cudaEventDisableTiming);
        cudaEventCreateWithFlags(&evB, cudaEventDisableTiming);
        cudaFuncSetAttribute(gemm_mma_kernel,
                             cudaFuncAttributeMaxDynamicSharedMemorySize, SM_TOTAL);
        init_done = true;
    }

    // fork: CSR build on s2 runs concurrently with GEMM on the main stream
    cudaEventRecord(evA, 0);
    cudaStreamWaitEvent(s2, evA, 0);

    // --- main stream: W prep + GEMM ---
    prep_w_kernel<<<(D_OUT * D_IN / 2 + 255) / 256, 256>>>(weight);
    gemm_mma_kernel<<<(n_nodes + 127) / 128, 256, SM_TOTAL>>>(x, n_nodes);

    // --- s2: CSR build ---
    zero_counts_kernel<<<(n_nodes + 255) / 256, 256, 0, s2>>>(n_nodes);
    hist_kernel<<<(n_edges + 255) / 256, 256, 0, s2>>>(edge_row, n_edges);
    {
        int nb = (n_nodes + 1023) / 1024;
        block_sum_kernel<<<nb, 1024, 0, s2>>>(n_nodes);
        bsum_scan_kernel<<<1, 64, 0, s2>>>(nb, n_nodes);
        scan_pass3_kernel<<<nb, 1024, 0, s2>>>(n_nodes);
    }
    bucket_kernel<<<(n_edges + 255) / 256, 256, 0, s2>>>(edge_val, edge_row, edge_col, n_edges);
    cudaEventRecord(evB, s2);

    // join, then gather
    cudaStreamWaitEvent(0, evB, 0);
    {
        int warps_per_block = 256 / 32;
        int grid = (n_nodes + warps_per_block - 1) / warps_per_block;
        gather_kernel<<<grid, 256>>>(bias, alpha, out, n_nodes);
    }
}